// round 1
// baseline (speedup 1.0000x reference)
#include <cuda_runtime.h>

// Problem constants
#define B_   2
#define N_   4
#define BN_  8
#define C_   64
#define HF_  64
#define WF_  64
#define XV_  128
#define YV_  128
#define ZV_  8
#define HW_  (HF_ * WF_)          // 4096
#define P_TOT (ZV_ * YV_ * XV_)   // 131072

// Scratch (allocations forbidden -> __device__ globals)
__device__ float g_mats[BN_ * 12];                  // P0,P1,P2 rows (4 floats each) per bn
__device__ float g_featsT[BN_ * HW_ * C_];          // feats transposed to (bn, h, w, c)

// ---------------------------------------------------------------------------
// Kernel 0: per-camera matrix precompute (8 cameras)
// P0 = fx*M0 + x0*M2 ; P1 = fy*M1 + y0*M2 ; P2 = M2
// where M = camX_T_cam0 = [R^T | -R^T t] of extrins, fx/fy/x0/y0 scaled by 1/8.
// ---------------------------------------------------------------------------
__global__ void precompute_mats_kernel(const float* __restrict__ intrins,
                                       const float* __restrict__ extrins) {
    int bn = threadIdx.x;
    if (bn >= BN_) return;
    const float* E = extrins + bn * 16;
    const float* K = intrins + bn * 16;

    float M[3][4];
#pragma unroll
    for (int i = 0; i < 3; i++) {
        float r0 = E[0 * 4 + i];   // rT[i][0] = E[0][i]
        float r1 = E[1 * 4 + i];
        float r2 = E[2 * 4 + i];
        M[i][0] = r0; M[i][1] = r1; M[i][2] = r2;
        M[i][3] = -(r0 * E[3] + r1 * E[7] + r2 * E[11]);
    }
    float fx = K[0] * 0.125f;   // K[0][0] * (64/512)
    float fy = K[5] * 0.125f;   // K[1][1]
    float x0 = K[2] * 0.125f;   // K[0][2]
    float y0 = K[6] * 0.125f;   // K[1][2]

    float* P = g_mats + bn * 12;
#pragma unroll
    for (int k = 0; k < 4; k++) {
        P[0 * 4 + k] = fx * M[0][k] + x0 * M[2][k];
        P[1 * 4 + k] = fy * M[1][k] + y0 * M[2][k];
        P[2 * 4 + k] = M[2][k];
    }
}

// ---------------------------------------------------------------------------
// Kernel 1: transpose feats (bn, c, hw) -> (bn, hw, c), tiled 32x32 in smem.
// Makes each bilinear-corner gather a contiguous 256B run of 64 channels.
// ---------------------------------------------------------------------------
__global__ void transpose_feats_kernel(const float* __restrict__ feats) {
    __shared__ float tile[32][33];
    int bn = blockIdx.z;
    int c0 = blockIdx.y * 32;   // channel tile (0 or 32)
    int p0 = blockIdx.x * 32;   // hw tile
    int tx = threadIdx.x;       // 0..31
    int ty = threadIdx.y;       // 0..7

    const float* in = feats + (size_t)bn * C_ * HW_;
#pragma unroll
    for (int k = 0; k < 4; k++) {
        int cy = ty + k * 8;
        tile[cy][tx] = in[(c0 + cy) * HW_ + p0 + tx];
    }
    __syncthreads();
    float* out = g_featsT + (size_t)bn * HW_ * C_;
#pragma unroll
    for (int k = 0; k < 4; k++) {
        int pr = ty + k * 8;
        out[(p0 + pr) * C_ + c0 + tx] = tile[tx][pr];
    }
}

// ---------------------------------------------------------------------------
// Kernel 2: main projection + bilinear gather + masked camera mean.
// One thread per (b, z, x, y) voxel, y fastest (matches output's innermost dim
// -> coalesced stores). 64 channels processed as 16 float4 chunks.
// ---------------------------------------------------------------------------
__global__ void __launch_bounds__(256) bev_unproject_kernel(float* __restrict__ out) {
    int t = blockIdx.x * 256 + threadIdx.x;
    int y = t & 127;
    int x = (t >> 7) & 127;
    int z = (t >> 14) & 7;
    int b = t >> 17;

    __shared__ float sm[BN_ * 12];
    if (threadIdx.x < BN_ * 12) sm[threadIdx.x] = g_mats[threadIdx.x];
    __syncthreads();

    // voxel center in cam0/ref coords
    float X = (float)x * 0.8f - 50.8f;
    float Y = (float)y * 0.8f - 50.8f;
    float Z = (float)z * 0.5f - 2.75f;

    int   o00[4], o10[4], o01[4], o11[4];   // float4 offsets into g_featsT
    float w00[4], w10[4], w01[4], w11[4];
    int mask = 0;

#pragma unroll
    for (int n = 0; n < 4; n++) {
        const float* P = sm + (b * 4 + n) * 12;
        float xp = P[0] * X + P[1] * Y + P[2]  * Z + P[3];
        float yp = P[4] * X + P[5] * Y + P[6]  * Z + P[7];
        float zc = P[8] * X + P[9] * Y + P[10] * Z + P[11];

        float denom = fmaxf(zc, 1e-6f);
        float sx = xp / denom;
        float sy = yp / denom;

        bool valid = (sx > -0.5f) & (sx < 63.5f) & (sy > -0.5f) & (sy < 63.5f) & (zc > 0.0f);

        w00[n] = w10[n] = w01[n] = w11[n] = 0.0f;
        o00[n] = o10[n] = o01[n] = o11[n] = 0;

        if (valid) {
            float px = sx - 0.5f, py = sy - 0.5f;
            float x0f = floorf(px), y0f = floorf(py);
            float wx = px - x0f,    wy = py - y0f;
            int xi = (int)x0f;      // in [-1, 62]
            int yi = (int)y0f;      // in [-1, 62]
            bool lv = (xi >= 0);    // left column valid
            bool tv = (yi >= 0);    // top row valid
            int xc = lv ? xi : 0;
            int yc = tv ? yi : 0;
            int bn = b * 4 + n;
            int base = ((bn * HF_ + yc) * WF_ + xc) * (C_ / 4);  // float4 units
            int dx = lv ? (C_ / 4) : 0;            // step to x0+1 (16 f4)
            int dy = tv ? (WF_ * (C_ / 4)) : 0;    // step to y0+1 (1024 f4)
            o00[n] = base;
            o10[n] = base + dx;
            o01[n] = base + dy;
            o11[n] = base + dx + dy;
            float fvx = lv ? 1.0f : 0.0f;
            float fvy = tv ? 1.0f : 0.0f;
            float omwx = 1.0f - wx, omwy = 1.0f - wy;
            w00[n] = omwx * omwy * fvx * fvy;
            w10[n] = wx   * omwy * fvy;
            w01[n] = omwx * wy   * fvx;
            w11[n] = wx   * wy;
            mask |= (1 << n);
        }
    }

    // reciprocals of (eps + count), count in {0..4}
    const float r0 = 1.0f / 1e-6f;
    const float r1 = 1.0f / (1e-6f + 1.0f);
    const float r2 = 1.0f / (1e-6f + 2.0f);
    const float r3 = 1.0f / (1e-6f + 3.0f);
    const float r4 = 1.0f / (1e-6f + 4.0f);

    const float4* __restrict__ F = (const float4*)g_featsT;
    // out[b, c*8+z, x, y] ; element index = ((b*64 + c)*8 + z)*16384 + x*128 + y
    int outbase = ((b * C_) * ZV_ + z) * (XV_ * YV_) + x * YV_ + y;
    const int cstride = ZV_ * XV_ * YV_;   // 131072

    for (int cc = 0; cc < C_ / 4; cc++) {
        float ax = 0.f, ay = 0.f, az = 0.f, aw = 0.f;
        float cx = 0.f, cy2 = 0.f, cz = 0.f, cw = 0.f;
#pragma unroll
        for (int n = 0; n < 4; n++) {
            if (mask & (1 << n)) {
                float4 g00 = __ldg(F + o00[n] + cc);
                float4 g10 = __ldg(F + o10[n] + cc);
                float4 g01 = __ldg(F + o01[n] + cc);
                float4 g11 = __ldg(F + o11[n] + cc);
                float a = w00[n], bw = w10[n], c2 = w01[n], d = w11[n];

                float vx = ((g00.x * a + g10.x * bw) + g01.x * c2) + g11.x * d;
                float vy = ((g00.y * a + g10.y * bw) + g01.y * c2) + g11.y * d;
                float vz = ((g00.z * a + g10.z * bw) + g01.z * c2) + g11.z * d;
                float vw = ((g00.w * a + g10.w * bw) + g01.w * c2) + g11.w * d;

                ax += vx; ay += vy; az += vz; aw += vw;
                cx  += (vx != 0.0f) ? 1.0f : 0.0f;
                cy2 += (vy != 0.0f) ? 1.0f : 0.0f;
                cz  += (vz != 0.0f) ? 1.0f : 0.0f;
                cw  += (vw != 0.0f) ? 1.0f : 0.0f;
            }
        }
        float rx = (cx  == 0.f) ? r0 : (cx  == 1.f) ? r1 : (cx  == 2.f) ? r2 : (cx  == 3.f) ? r3 : r4;
        float ry = (cy2 == 0.f) ? r0 : (cy2 == 1.f) ? r1 : (cy2 == 2.f) ? r2 : (cy2 == 3.f) ? r3 : r4;
        float rz = (cz  == 0.f) ? r0 : (cz  == 1.f) ? r1 : (cz  == 2.f) ? r2 : (cz  == 3.f) ? r3 : r4;
        float rw = (cw  == 0.f) ? r0 : (cw  == 1.f) ? r1 : (cw  == 2.f) ? r2 : (cw  == 3.f) ? r3 : r4;

        int c = 4 * cc;
        out[outbase + (c + 0) * cstride] = ax * rx;
        out[outbase + (c + 1) * cstride] = ay * ry;
        out[outbase + (c + 2) * cstride] = az * rz;
        out[outbase + (c + 3) * cstride] = aw * rw;
    }
}

// ---------------------------------------------------------------------------
extern "C" void kernel_launch(void* const* d_in, const int* in_sizes, int n_in,
                              void* d_out, int out_size) {
    const float* feats   = (const float*)d_in[0];  // (2,4,64,64,64)
    const float* intrins = (const float*)d_in[1];  // (2,4,4,4)
    const float* extrins = (const float*)d_in[2];  // (2,4,4,4)
    float* out = (float*)d_out;                    // (2,512,128,128)

    precompute_mats_kernel<<<1, 32>>>(intrins, extrins);

    dim3 tgrid(HW_ / 32, C_ / 32, BN_);
    dim3 tblock(32, 8);
    transpose_feats_kernel<<<tgrid, tblock>>>(feats);

    int total = B_ * P_TOT;           // 262144 threads
    bev_unproject_kernel<<<total / 256, 256>>>(out);
}